// round 3
// baseline (speedup 1.0000x reference)
#include <cuda_runtime.h>

#define N_NODES 100000
#define N_EDGES 800000
#define IN_CH 128
#define HID 128
#define OUT_CH 64

// ---------------- scratch (static device memory; no runtime alloc) ----------------
__device__ float g_A[N_NODES * HID];      // GEMM output buffer
__device__ float g_B[N_NODES * HID];      // aggregation output buffer
__device__ float g_dinv[N_NODES];
__device__ int   g_count[N_NODES + 1];
__device__ int   g_scan[N_NODES + 1];
__device__ int   g_rowptr[N_NODES + 1];
__device__ int   g_cursor[N_NODES];
__device__ int   g_srcs[N_EDGES];
__device__ int   g_bsum[128];

// ---------------- CSR build ----------------
__global__ void k_zero_count() {
    int i = blockIdx.x * blockDim.x + threadIdx.x;
    if (i <= N_NODES) g_count[i] = 0;
}

__global__ void k_hist(const int* __restrict__ dst) {
    int e = blockIdx.x * blockDim.x + threadIdx.x;
    if (e < N_EDGES) {
        int d = dst[e];
        if ((unsigned)d < (unsigned)N_NODES) atomicAdd(&g_count[d], 1);
    }
}

__global__ void k_dinv() {
    int i = blockIdx.x * blockDim.x + threadIdx.x;
    if (i < N_NODES) g_dinv[i] = rsqrtf((float)g_count[i] + 1.0f);
}

// block-level inclusive scan (1024 elems per block)
__global__ void k_scan1() {
    __shared__ int s[1024];
    int lt = threadIdx.x;
    int i = blockIdx.x * 1024 + lt;
    int v = (i <= N_NODES) ? g_count[i] : 0;
    s[lt] = v;
    __syncthreads();
    for (int off = 1; off < 1024; off <<= 1) {
        int t = (lt >= off) ? s[lt - off] : 0;
        __syncthreads();
        s[lt] += t;
        __syncthreads();
    }
    if (i <= N_NODES) g_scan[i] = s[lt];
    if (lt == 1023) g_bsum[blockIdx.x] = s[1023];
}

__global__ void k_scan2(int nb) {
    if (threadIdx.x == 0 && blockIdx.x == 0) {
        int run = 0;
        for (int b = 0; b < nb; b++) { int v = g_bsum[b]; g_bsum[b] = run; run += v; }
    }
}

__global__ void k_scan3() {
    int i = blockIdx.x * 1024 + threadIdx.x;
    if (i <= N_NODES) {
        int ex = g_scan[i] - g_count[i] + g_bsum[blockIdx.x];
        g_rowptr[i] = ex;
        if (i < N_NODES) g_cursor[i] = ex;
    }
}

__global__ void k_scatter(const int* __restrict__ ei) {
    int e = blockIdx.x * blockDim.x + threadIdx.x;
    if (e < N_EDGES) {
        int s = ei[e];
        int d = ei[N_EDGES + e];
        if ((unsigned)s < (unsigned)N_NODES && (unsigned)d < (unsigned)N_NODES) {
            int pos = atomicAdd(&g_cursor[d], 1);
            if ((unsigned)pos < (unsigned)N_EDGES) g_srcs[pos] = s;
        }
    }
}

// ---------------- GEMM: Y[N,C] = X[N,128] @ W[128,C] ----------------
// 256 threads/block. Whole K staged once. Per-thread 8 rows x 4 cols micro-tile.
template <int C>
__global__ void k_gemm(const float* __restrict__ X, const float* __restrict__ W,
                       float* __restrict__ Y) {
    constexpr int CG = C / 4;        // float4 col groups
    constexpr int RG = 256 / CG;     // row groups
    constexpr int ROWS = RG * 8;     // rows per block
    extern __shared__ float4 sm[];
    float4* Xs = sm;                 // [ROWS][32]
    float4* Ws = sm + ROWS * 32;     // [128][CG]

    int t = threadIdx.x;
    int rowBase = blockIdx.x * ROWS;

    const float4* X4 = reinterpret_cast<const float4*>(X);
    const float4* W4 = reinterpret_cast<const float4*>(W);

#pragma unroll
    for (int j = 0; j < ROWS * 32 / 256; j++) {
        int fi = t + j * 256;
        int r = fi >> 5, c4 = fi & 31;
        int gr = rowBase + r;
        Xs[fi] = (gr < N_NODES) ? X4[gr * 32 + c4] : make_float4(0.f, 0.f, 0.f, 0.f);
    }
#pragma unroll
    for (int j = 0; j < 128 * CG / 256; j++) {
        int fi = t + j * 256;
        Ws[fi] = W4[fi];
    }
    __syncthreads();

    int cg = t % CG;
    int r0 = (t / CG) * 8;

    float acc[8][4];
#pragma unroll
    for (int i = 0; i < 8; i++)
#pragma unroll
        for (int c = 0; c < 4; c++) acc[i][c] = 0.f;

#pragma unroll 4
    for (int k4 = 0; k4 < 32; k4++) {
        float4 w0 = Ws[(k4 * 4 + 0) * CG + cg];
        float4 w1 = Ws[(k4 * 4 + 1) * CG + cg];
        float4 w2 = Ws[(k4 * 4 + 2) * CG + cg];
        float4 w3 = Ws[(k4 * 4 + 3) * CG + cg];
#pragma unroll
        for (int i = 0; i < 8; i++) {
            float4 xv = Xs[(r0 + i) * 32 + k4];
            acc[i][0] = fmaf(xv.x, w0.x, fmaf(xv.y, w1.x, fmaf(xv.z, w2.x, fmaf(xv.w, w3.x, acc[i][0]))));
            acc[i][1] = fmaf(xv.x, w0.y, fmaf(xv.y, w1.y, fmaf(xv.z, w2.y, fmaf(xv.w, w3.y, acc[i][1]))));
            acc[i][2] = fmaf(xv.x, w0.z, fmaf(xv.y, w1.z, fmaf(xv.z, w2.z, fmaf(xv.w, w3.z, acc[i][2]))));
            acc[i][3] = fmaf(xv.x, w0.w, fmaf(xv.y, w1.w, fmaf(xv.z, w2.w, fmaf(xv.w, w3.w, acc[i][3]))));
        }
    }

    float4* Y4 = reinterpret_cast<float4*>(Y);
#pragma unroll
    for (int i = 0; i < 8; i++) {
        int gr = rowBase + r0 + i;
        if (gr < N_NODES)
            Y4[gr * CG + cg] = make_float4(acc[i][0], acc[i][1], acc[i][2], acc[i][3]);
    }
}

// smem bytes per instantiation
template <int C>
constexpr int gemm_smem() {
    constexpr int CG = C / 4;
    constexpr int ROWS = (256 / CG) * 8;
    return (ROWS * 32 + 128 * CG) * 16;
}

// ---------------- Aggregation: out = dinv[n]*(sum dinv[s]*h[s] + dinv[n]*h[n]) + b ----------------
// One warp per node, gather from CSR, no atomics. Fuses self-loop, bias, relu.
template <int C, bool RELU>
__global__ void k_agg(const float* __restrict__ H, const float* __restrict__ bias,
                      float* __restrict__ out) {
    constexpr int LANES = C / 4;
    int gtid = blockIdx.x * blockDim.x + threadIdx.x;
    int node = gtid >> 5;
    int lane = threadIdx.x & 31;
    if (node >= N_NODES || lane >= LANES) return;

    int start = g_rowptr[node];
    int end   = g_rowptr[node + 1];
    float dn  = g_dinv[node];

    const float4* H4 = reinterpret_cast<const float4*>(H);
    float4 acc = make_float4(0.f, 0.f, 0.f, 0.f);
    for (int e = start; e < end; e++) {
        int s = g_srcs[e];
        float w = g_dinv[s];
        float4 v = H4[s * LANES + lane];
        acc.x = fmaf(w, v.x, acc.x);
        acc.y = fmaf(w, v.y, acc.y);
        acc.z = fmaf(w, v.z, acc.z);
        acc.w = fmaf(w, v.w, acc.w);
    }
    float4 hs = H4[node * LANES + lane];
    float4 bv = reinterpret_cast<const float4*>(bias)[lane];
    acc.x = fmaf(fmaf(dn, hs.x, acc.x), dn, bv.x);
    acc.y = fmaf(fmaf(dn, hs.y, acc.y), dn, bv.y);
    acc.z = fmaf(fmaf(dn, hs.z, acc.z), dn, bv.z);
    acc.w = fmaf(fmaf(dn, hs.w, acc.w), dn, bv.w);
    if (RELU) {
        acc.x = fmaxf(acc.x, 0.f);
        acc.y = fmaxf(acc.y, 0.f);
        acc.z = fmaxf(acc.z, 0.f);
        acc.w = fmaxf(acc.w, 0.f);
    }
    reinterpret_cast<float4*>(out)[node * LANES + lane] = acc;
}

// ---------------- launch ----------------
extern "C" void kernel_launch(void* const* d_in, const int* in_sizes, int n_in,
                              void* d_out, int out_size) {
    const float* x  = (const float*)d_in[0];
    const int*   ei = (const int*)d_in[1];   // int32! JAX x64 disabled downgrades int64->int32
    const float* W1 = (const float*)d_in[2];
    const float* b1 = (const float*)d_in[3];
    const float* W2 = (const float*)d_in[4];
    const float* b2 = (const float*)d_in[5];
    const float* W3 = (const float*)d_in[6];
    const float* b3 = (const float*)d_in[7];
    float* out = (float*)d_out;

    (void)in_sizes; (void)n_in; (void)out_size;

    constexpr int SMEM128 = gemm_smem<128>();  // 96 KB
    constexpr int SMEM64  = gemm_smem<64>();   // 96 KB
    cudaFuncSetAttribute(k_gemm<128>, cudaFuncAttributeMaxDynamicSharedMemorySize, SMEM128);
    cudaFuncSetAttribute(k_gemm<64>,  cudaFuncAttributeMaxDynamicSharedMemorySize, SMEM64);

    float* A; float* B;
    cudaGetSymbolAddress((void**)&A, g_A);
    cudaGetSymbolAddress((void**)&B, g_B);

    const int NB_SCAN = (N_NODES + 1 + 1023) / 1024;  // 98

    k_zero_count<<<(N_NODES + 1 + 255) / 256, 256>>>();
    k_hist<<<(N_EDGES + 255) / 256, 256>>>(ei + N_EDGES);
    k_dinv<<<(N_NODES + 255) / 256, 256>>>();
    k_scan1<<<NB_SCAN, 1024>>>();
    k_scan2<<<1, 32>>>(NB_SCAN);
    k_scan3<<<NB_SCAN, 1024>>>();
    k_scatter<<<(N_EDGES + 255) / 256, 256>>>(ei);

    const int AGG_BLOCKS = (N_NODES * 32 + 255) / 256;  // 12500

    // layer 1
    k_gemm<128><<<(N_NODES + 63) / 64, 256, SMEM128>>>(x, W1, A);
    k_agg<128, true><<<AGG_BLOCKS, 256>>>(A, b1, B);
    // layer 2
    k_gemm<128><<<(N_NODES + 63) / 64, 256, SMEM128>>>(B, W2, A);
    k_agg<128, true><<<AGG_BLOCKS, 256>>>(A, b2, B);
    // layer 3
    k_gemm<64><<<(N_NODES + 127) / 128, 256, SMEM64>>>(B, W3, A);
    k_agg<64, false><<<AGG_BLOCKS, 256>>>(A, b3, out);
}